// round 1
// baseline (speedup 1.0000x reference)
#include <cuda_runtime.h>
#include <math.h>
#include <float.h>

// Problem constants (fixed by the reference)
#define BB 16
#define NS 4096
#define NQ 4096
#define DD 512
#define CC 128

#define GEMM_BLOCKS (BB * (NQ / 128))   // 16 * 32 = 512

// Scratch (static __device__ — no runtime allocation)
__device__ float g_protosT[(size_t)BB * DD * CC];   // [b][d][c], 4 MB
__device__ float g_psq[BB * CC];
__device__ float g_loss_part[GEMM_BLOCKS];
__device__ int   g_corr_part[GEMM_BLOCKS];

// ---------------------------------------------------------------------------
// Kernel 1: prototypes. Grid (4 d-groups, 16 batches), 128 threads.
// Thread t owns d-lane (dg*128 + t). Accumulates class sums in smem
// (column-exclusive, race-free). Counts via smem atomicAdd of exact
// integers (order-independent => deterministic). Writes protos TRANSPOSED
// [b][d][c] so the GEMM can load [k][c] tiles coalesced.
// ---------------------------------------------------------------------------
__global__ void proto_kernel(const float* __restrict__ sup,
                             const int* __restrict__ stgt) {
    extern __shared__ float sm[];
    float* acc = sm;            // [128 classes][128 d-lanes]
    float* cnt = sm + 128 * 128;

    const int t  = threadIdx.x;
    const int dg = blockIdx.x;
    const int b  = blockIdx.y;

    #pragma unroll 4
    for (int c = 0; c < CC; c++) acc[c * 128 + t] = 0.0f;
    cnt[t] = 0.0f;
    __syncthreads();

    const int* tg = stgt + (size_t)b * NS;
    for (int n = t; n < NS; n += 128) atomicAdd(&cnt[tg[n]], 1.0f);

    const float* supb = sup + (size_t)b * NS * DD + dg * 128 + t;
    for (int n0 = 0; n0 < NS; n0 += 8) {
        int   cc[8];
        float vv[8];
        #pragma unroll
        for (int u = 0; u < 8; u++) {
            cc[u] = tg[n0 + u];
            vv[u] = supb[(size_t)(n0 + u) * DD];
        }
        #pragma unroll
        for (int u = 0; u < 8; u++)
            acc[cc[u] * 128 + t] += vv[u];
    }
    __syncthreads();

    float* dst = g_protosT + ((size_t)b * DD + dg * 128 + t) * CC;
    for (int c = 0; c < CC; c += 4) {
        float4 w;
        w.x = acc[(c + 0) * 128 + t] / fmaxf(cnt[c + 0], 1.0f);
        w.y = acc[(c + 1) * 128 + t] / fmaxf(cnt[c + 1], 1.0f);
        w.z = acc[(c + 2) * 128 + t] / fmaxf(cnt[c + 2], 1.0f);
        w.w = acc[(c + 3) * 128 + t] / fmaxf(cnt[c + 3], 1.0f);
        *(float4*)(dst + c) = w;
    }
}

// ---------------------------------------------------------------------------
// Kernel 2: ||proto||^2 per (b, c). Grid 16, block 128 (thread = class).
// Reads protosT[b][d][c] — coalesced across threads at fixed d.
// ---------------------------------------------------------------------------
__global__ void psq_kernel() {
    const int b = blockIdx.x;
    const int c = threadIdx.x;
    const float* p = g_protosT + (size_t)b * DD * CC + c;
    float s = 0.0f;
    #pragma unroll 8
    for (int d = 0; d < DD; d++) {
        float v = p[(size_t)d * CC];
        s = fmaf(v, v, s);
    }
    g_psq[b * CC + c] = s;
}

// ---------------------------------------------------------------------------
// Kernel 3: fused distance GEMM + argmin + softmax-CE epilogue.
// Grid (32 q-tiles, 16 b), 256 threads (tx = tid&15, ty = tid>>4).
// Tile: 128 classes x 128 queries, K-chunks of 32.
// Fragment map: c_i = ty + 16*i, q_j = tx + 16*j  (conflict-free LDS).
// dist = p_sq[c] - 2*cross  (q_sq cancels in argmin/softmax/NLL).
// ---------------------------------------------------------------------------
__global__ __launch_bounds__(256, 2)
void gemm_kernel(const float* __restrict__ qry,
                 const int* __restrict__ qtgt,
                 float* __restrict__ pred_out) {
    __shared__ union {
        struct { float As[32][128]; float Bs[32][129]; } g;   // 32.6 KB
        struct { float rmin[16][128]; int rarg[16][128];
                 float rsum[16][128]; float rtl[128]; } r;    // 24.5 KB
    } sm;

    const int tid = threadIdx.x;
    const int tx  = tid & 15;
    const int ty  = tid >> 4;
    const int qt  = blockIdx.x;
    const int b   = blockIdx.y;
    const int q0  = qt * 128;

    float acc[8][8];
    #pragma unroll
    for (int i = 0; i < 8; i++)
        #pragma unroll
        for (int j = 0; j < 8; j++) acc[i][j] = 0.0f;

    const float* Ab = g_protosT + (size_t)b * DD * CC;
    const float* Qb = qry + ((size_t)b * NQ + q0) * DD;

    for (int k0 = 0; k0 < DD; k0 += 32) {
        // Load A tile: protosT[b][k0+row][c] -> As[row][c], coalesced float4
        #pragma unroll
        for (int p = 0; p < 4; p++) {
            int row = tid >> 3;
            int c4  = (tid & 7) + p * 8;
            *(float4*)&sm.g.As[row][c4 * 4] =
                *(const float4*)(Ab + (size_t)(k0 + row) * CC + c4 * 4);
        }
        // Load B tile: queries[b][q][k] transposed -> Bs[k][q] (pitch 129)
        #pragma unroll
        for (int p = 0; p < 4; p++) {
            int qr = (tid >> 3) + p * 32;
            int k4 = tid & 7;
            float4 v = *(const float4*)(Qb + (size_t)qr * DD + k0 + k4 * 4);
            sm.g.Bs[k4 * 4 + 0][qr] = v.x;
            sm.g.Bs[k4 * 4 + 1][qr] = v.y;
            sm.g.Bs[k4 * 4 + 2][qr] = v.z;
            sm.g.Bs[k4 * 4 + 3][qr] = v.w;
        }
        __syncthreads();

        #pragma unroll
        for (int kk = 0; kk < 32; kk++) {
            float a[8], bb[8];
            #pragma unroll
            for (int i = 0; i < 8; i++) a[i]  = sm.g.As[kk][ty + 16 * i];
            #pragma unroll
            for (int j = 0; j < 8; j++) bb[j] = sm.g.Bs[kk][tx + 16 * j];
            #pragma unroll
            for (int i = 0; i < 8; i++)
                #pragma unroll
                for (int j = 0; j < 8; j++)
                    acc[i][j] = fmaf(a[i], bb[j], acc[i][j]);
        }
        __syncthreads();
    }

    // dist[i][j] = p_sq[c_i] - 2*cross (in place)
    #pragma unroll
    for (int i = 0; i < 8; i++) {
        float ps = g_psq[b * CC + ty + 16 * i];
        #pragma unroll
        for (int j = 0; j < 8; j++)
            acc[i][j] = ps - 2.0f * acc[i][j];
    }

    // Pass 1: local min/argmin over this thread's 8 classes per query.
    float lmin[8]; int larg[8];
    #pragma unroll
    for (int j = 0; j < 8; j++) {
        lmin[j] = acc[0][j];
        larg[j] = ty;
        #pragma unroll
        for (int i = 1; i < 8; i++) {
            float v = acc[i][j];
            if (v < lmin[j]) { lmin[j] = v; larg[j] = ty + 16 * i; }
        }
    }
    #pragma unroll
    for (int j = 0; j < 8; j++) {
        int qj = tx + 16 * j;
        sm.r.rmin[ty][qj] = lmin[j];
        sm.r.rarg[ty][qj] = larg[j];
    }
    __syncthreads();

    // Global min/argmin (jax tie-break: lowest class index wins)
    float gmin[8]; int garg[8];
    #pragma unroll
    for (int j = 0; j < 8; j++) {
        int qj = tx + 16 * j;
        float g = FLT_MAX; int ga = CC;
        #pragma unroll
        for (int yy = 0; yy < 16; yy++) {
            float v = sm.r.rmin[yy][qj];
            int   a = sm.r.rarg[yy][qj];
            if (v < g || (v == g && a < ga)) { g = v; ga = a; }
        }
        gmin[j] = g; garg[j] = ga;
    }

    // Targets for this thread's 8 queries
    int tg8[8];
    #pragma unroll
    for (int j = 0; j < 8; j++)
        tg8[j] = qtgt[(size_t)b * NQ + q0 + tx + 16 * j];

    // Pass 2: exp-sum (args <= 0, no overflow) + target-class distance
    #pragma unroll
    for (int j = 0; j < 8; j++) {
        int qj = tx + 16 * j;
        float g = gmin[j];
        float s = 0.0f;
        #pragma unroll
        for (int i = 0; i < 8; i++)
            s += expf(g - acc[i][j]);
        sm.r.rsum[ty][qj] = s;
        #pragma unroll
        for (int i = 0; i < 8; i++)
            if (ty + 16 * i == tg8[j]) sm.r.rtl[qj] = acc[i][j];
    }
    __syncthreads();

    // ty==0 lane (tid 0..15) finishes each query; deterministic fixed-order sums
    if (ty == 0) {
        float lsum = 0.0f; int csum = 0;
        #pragma unroll
        for (int j = 0; j < 8; j++) {
            int qj = tx + 16 * j;
            float S = 0.0f;
            #pragma unroll
            for (int yy = 0; yy < 16; yy++) S += sm.r.rsum[yy][qj];
            float nll = sm.r.rtl[qj] - gmin[j] + logf(S);
            lsum += nll;
            csum += (garg[j] == tg8[j]);
            if (pred_out)
                pred_out[(size_t)b * NQ + q0 + qj] = (float)garg[j];
        }
        #pragma unroll
        for (int o = 8; o > 0; o >>= 1) {
            lsum += __shfl_down_sync(0xFFFFu, lsum, o);
            csum += __shfl_down_sync(0xFFFFu, csum, o);
        }
        if (tid == 0) {
            int bid = b * (NQ / 128) + qt;
            g_loss_part[bid] = lsum;
            g_corr_part[bid] = csum;
        }
    }
}

// ---------------------------------------------------------------------------
// Kernel 4: deterministic fixed-order final reduction + tail writes.
// ---------------------------------------------------------------------------
__global__ void finalize_kernel(float* __restrict__ out, int out_size) {
    __shared__ float sl[GEMM_BLOCKS];
    __shared__ int   sc[GEMM_BLOCKS];
    int t = threadIdx.x;
    sl[t] = g_loss_part[t];
    sc[t] = g_corr_part[t];
    __syncthreads();
    for (int s = GEMM_BLOCKS / 2; s > 0; s >>= 1) {
        if (t < s) { sl[t] += sl[t + s]; sc[t] += sc[t + s]; }
        __syncthreads();
    }
    if (t == 0) {
        const float inv = 1.0f / (float)(BB * NQ);
        float loss = sl[0] * inv;
        float accu = (float)sc[0] * inv;
        if (out_size >= BB * NQ + 2) {
            out[BB * NQ]     = loss;
            out[BB * NQ + 1] = accu;
        } else if (out_size == 2) {
            out[0] = loss;
            out[1] = accu;
        } else if (out_size == 1) {
            out[0] = loss;
        }
    }
}

// ---------------------------------------------------------------------------
extern "C" void kernel_launch(void* const* d_in, const int* in_sizes, int n_in,
                              void* d_out, int out_size) {
    const float* sup  = (const float*)d_in[0];
    const float* qry  = (const float*)d_in[1];
    const int*   stgt = (const int*)d_in[2];
    const int*   qtgt = (const int*)d_in[3];
    float* out = (float*)d_out;

    const int proto_smem = (128 * 128 + 128) * sizeof(float);  // 66 KB
    cudaFuncSetAttribute(proto_kernel,
                         cudaFuncAttributeMaxDynamicSharedMemorySize,
                         proto_smem);

    proto_kernel<<<dim3(DD / 128, BB), 128, proto_smem>>>(sup, stgt);
    psq_kernel<<<BB, CC>>>();

    float* pred_out = (out_size >= BB * NQ) ? out : nullptr;
    gemm_kernel<<<dim3(NQ / 128, BB), 256>>>(qry, qtgt, pred_out);

    finalize_kernel<<<1, GEMM_BLOCKS>>>(out, out_size);
}

// round 3
// speedup vs baseline: 1.9467x; 1.9467x over previous
#include <cuda_runtime.h>
#include <cuda_bf16.h>
#include <math.h>
#include <float.h>
#include <stdint.h>

#define BB 16
#define NS 4096
#define NQ 4096
#define DD 512
#define CC 128
#define SPLIT 8
#define GEMM_BLOCKS (BB * (NQ / 128))   // 512

// ---------------- static device scratch (no runtime alloc) ----------------
__device__ float g_part[(size_t)SPLIT * BB * 4 * CC * 128];   // 32 MB
__device__ float g_cnt_part[SPLIT * BB * CC];
__device__ __nv_bfloat16 g_proto_h[(size_t)BB * CC * DD];     // [b][c][d]
__device__ __nv_bfloat16 g_proto_m[(size_t)BB * CC * DD];
__device__ __nv_bfloat16 g_proto_l[(size_t)BB * CC * DD];
__device__ float g_psq[BB * CC];
__device__ float g_loss_part[GEMM_BLOCKS];
__device__ int   g_corr_part[GEMM_BLOCKS];

// ---------------- helpers ----------------
__device__ __forceinline__ uint32_t smem_u32(const void* p) {
    uint32_t a;
    asm("{ .reg .u64 t; cvta.to.shared.u64 t, %1; cvt.u32.u64 %0, t; }" : "=r"(a) : "l"(p));
    return a;
}
__device__ __forceinline__ void ldsm4(uint32_t* r, uint32_t addr) {
    asm volatile("ldmatrix.sync.aligned.m8n8.x4.shared.b16 {%0,%1,%2,%3}, [%4];"
                 : "=r"(r[0]), "=r"(r[1]), "=r"(r[2]), "=r"(r[3]) : "r"(addr));
}
__device__ __forceinline__ void mma_bf16(float* c, const uint32_t* a,
                                         uint32_t b0, uint32_t b1) {
    asm volatile("mma.sync.aligned.m16n8k16.row.col.f32.bf16.bf16.f32 "
                 "{%0,%1,%2,%3}, {%4,%5,%6,%7}, {%8,%9}, {%0,%1,%2,%3};"
                 : "+f"(c[0]), "+f"(c[1]), "+f"(c[2]), "+f"(c[3])
                 : "r"(a[0]), "r"(a[1]), "r"(a[2]), "r"(a[3]), "r"(b0), "r"(b1));
}
__device__ __forceinline__ void split3(float v, __nv_bfloat16& h, __nv_bfloat16& m,
                                       __nv_bfloat16& l) {
    h = __float2bfloat16_rn(v);
    float r1 = v - __bfloat162float(h);
    m = __float2bfloat16_rn(r1);
    float r2 = r1 - __bfloat162float(m);
    l = __float2bfloat16_rn(r2);
}
__device__ __forceinline__ uint32_t pkbf(__nv_bfloat16 a, __nv_bfloat16 b) {
    __nv_bfloat162 t = __halves2bfloat162(a, b);
    return *reinterpret_cast<uint32_t*>(&t);
}

// ---------------------------------------------------------------------------
// Kernel 1: split prototype accumulation. Grid (4 dg, 16 b, 8 split), 128 thr.
// ---------------------------------------------------------------------------
__global__ void proto_kernel(const float* __restrict__ sup,
                             const int* __restrict__ stgt) {
    extern __shared__ float sm[];
    float* acc = sm;             // [128 c][128 dlane]
    float* cnt = sm + CC * 128;

    const int t = threadIdx.x, dg = blockIdx.x, b = blockIdx.y, sp = blockIdx.z;

    #pragma unroll 4
    for (int c = 0; c < CC; c++) acc[c * 128 + t] = 0.0f;
    cnt[t] = 0.0f;
    __syncthreads();

    const int* tg = stgt + (size_t)b * NS + sp * (NS / SPLIT);
    if (dg == 0)
        for (int n = t; n < NS / SPLIT; n += 128) atomicAdd(&cnt[tg[n]], 1.0f);

    const float* supb = sup + ((size_t)b * NS + sp * (NS / SPLIT)) * DD + dg * 128 + t;
    for (int n0 = 0; n0 < NS / SPLIT; n0 += 16) {
        int cc16[16]; float vv[16];
        #pragma unroll
        for (int u = 0; u < 16; u++) {
            cc16[u] = tg[n0 + u];
            vv[u] = supb[(size_t)(n0 + u) * DD];
        }
        #pragma unroll
        for (int u = 0; u < 16; u++) acc[cc16[u] * 128 + t] += vv[u];
    }
    __syncthreads();

    float* dst = g_part + ((((size_t)sp * BB + b) * 4 + dg) * CC) * 128 + t;
    for (int c = 0; c < CC; c++) dst[(size_t)c * 128] = acc[c * 128 + t];
    if (dg == 0) g_cnt_part[(sp * BB + b) * CC + t] = cnt[t];
}

// ---------------------------------------------------------------------------
// Kernel 2: deterministic reduce -> bf16 h/m/l protos + p_sq.
// Grid (128 c, 16 b), 128 threads.
// ---------------------------------------------------------------------------
__global__ void reduce_kernel() {
    const int c = blockIdx.x, b = blockIdx.y, t = threadIdx.x;

    float cntv = 0.0f;
    #pragma unroll
    for (int s = 0; s < SPLIT; s++) cntv += g_cnt_part[(s * BB + b) * CC + c];
    const float inv = 1.0f / fmaxf(cntv, 1.0f);

    float psq = 0.0f;
    #pragma unroll
    for (int dg = 0; dg < 4; dg++) {
        float v = 0.0f;
        #pragma unroll
        for (int s = 0; s < SPLIT; s++)
            v += g_part[(((size_t)s * BB + b) * 4 + dg) * CC * 128 + (size_t)c * 128 + t];
        float mean = v * inv;
        __nv_bfloat16 h, m, l;
        split3(mean, h, m, l);
        size_t o = ((size_t)b * CC + c) * DD + dg * 128 + t;
        g_proto_h[o] = h; g_proto_m[o] = m; g_proto_l[o] = l;
        psq = fmaf(mean, mean, psq);
    }
    __shared__ float r[128];
    r[t] = psq;
    __syncthreads();
    for (int s = 64; s > 0; s >>= 1) {
        if (t < s) r[t] += r[t + s];
        __syncthreads();
    }
    if (t == 0) g_psq[b * CC + c] = r[0];
}

// ---------------------------------------------------------------------------
// Kernel 3: mma.sync bf16 distance GEMM (3-way split, 6 passes) + fused
// argmin / softmax-CE epilogue. Grid (32 qtiles, 16 b), 256 threads.
//
// Operand tiles in smem (per 64-k chunk), SW128 XOR swizzle, 16 KB each:
//   A_{h,m,l}: [128 c][64 k] bf16,  B_{h,m,l}: [128 q][64 k] bf16
// ldmatrix.x4 gives conflict-free A (row-major) and B (col-major) fragments.
// Warp layout: mw = wid&3 (32 classes), nw = wid>>2 (64 queries).
// ---------------------------------------------------------------------------
#define SA_H 0
#define SA_M 16384
#define SA_L 32768
#define SB_H 49152
#define SB_M 65536
#define SB_L 81920
#define SMEM_GEMM 98304

__global__ __launch_bounds__(256, 2)
void gemm_kernel(const float* __restrict__ qry,
                 const int* __restrict__ qtgt,
                 float* __restrict__ pred_out) {
    extern __shared__ char smem[];
    const uint32_t smb = smem_u32(smem);
    float* dist   = (float*)smem;            // [128 c][130] fp32 = 66560 B
    float* redmin = (float*)(smem + 66560);
    int*   redarg = (int*)  (smem + 67584);
    float* redsum = (float*)(smem + 68608);

    const int tid = threadIdx.x, wid = tid >> 5, lane = tid & 31;
    const int mw = wid & 3, nw = wid >> 2;
    const int qt = blockIdx.x, b = blockIdx.y, q0 = qt * 128;

    const float* Qb = qry + ((size_t)b * NQ + q0) * DD;
    const __nv_bfloat16* Ah = g_proto_h + (size_t)b * CC * DD;
    const __nv_bfloat16* Am = g_proto_m + (size_t)b * CC * DD;
    const __nv_bfloat16* Al = g_proto_l + (size_t)b * CC * DD;

    float acc[2][8][4];
    #pragma unroll
    for (int i = 0; i < 2; i++)
        #pragma unroll
        for (int j = 0; j < 8; j++)
            #pragma unroll
            for (int k = 0; k < 4; k++) acc[i][j][k] = 0.0f;

    // per-lane ldmatrix address components
    const uint32_t rowTerm = (uint32_t)(lane & 15) << 7;   // (L&15)*128
    const uint32_t sel16   = (uint32_t)(lane & 16);
    const uint32_t laneXor = (uint32_t)(lane & 7) << 4;

    static const uint32_t aoff[6] = {SA_H, SA_H, SA_M, SA_H, SA_L, SA_M};
    static const uint32_t boff[6] = {SB_H, SB_M, SB_H, SB_L, SB_H, SB_M};

    for (int k0 = 0; k0 < DD; k0 += 64) {
        if (k0) __syncthreads();
        // ---- stage A tiles (plain bf16 copy, swizzled) ----
        #pragma unroll
        for (int p = 0; p < 4; p++) {
            int idx = p * 256 + tid;            // 0..1023
            int row = idx >> 3, c16 = idx & 7;
            uint32_t sw = (uint32_t)(row * 128 + c16 * 16) ^ ((uint32_t)(row & 7) << 4);
            size_t go = (size_t)row * DD + k0 + c16 * 8;
            *(uint4*)(smem + SA_H + sw) = *(const uint4*)(Ah + go);
            *(uint4*)(smem + SA_M + sw) = *(const uint4*)(Am + go);
            *(uint4*)(smem + SA_L + sw) = *(const uint4*)(Al + go);
        }
        // ---- stage B tiles (fp32 load, 3-way split, swizzled) ----
        #pragma unroll
        for (int p = 0; p < 4; p++) {
            int idx = p * 256 + tid;
            int row = idx >> 3, c16 = idx & 7;
            const float* src = Qb + (size_t)row * DD + k0 + c16 * 8;
            float4 v0 = *(const float4*)(src);
            float4 v1 = *(const float4*)(src + 4);
            __nv_bfloat16 h[8], m[8], l[8];
            split3(v0.x, h[0], m[0], l[0]); split3(v0.y, h[1], m[1], l[1]);
            split3(v0.z, h[2], m[2], l[2]); split3(v0.w, h[3], m[3], l[3]);
            split3(v1.x, h[4], m[4], l[4]); split3(v1.y, h[5], m[5], l[5]);
            split3(v1.z, h[6], m[6], l[6]); split3(v1.w, h[7], m[7], l[7]);
            uint32_t sw = (uint32_t)(row * 128 + c16 * 16) ^ ((uint32_t)(row & 7) << 4);
            *(uint4*)(smem + SB_H + sw) =
                make_uint4(pkbf(h[0], h[1]), pkbf(h[2], h[3]), pkbf(h[4], h[5]), pkbf(h[6], h[7]));
            *(uint4*)(smem + SB_M + sw) =
                make_uint4(pkbf(m[0], m[1]), pkbf(m[2], m[3]), pkbf(m[4], m[5]), pkbf(m[6], m[7]));
            *(uint4*)(smem + SB_L + sw) =
                make_uint4(pkbf(l[0], l[1]), pkbf(l[2], l[3]), pkbf(l[4], l[5]), pkbf(l[6], l[7]));
        }
        __syncthreads();

        // ---- 6 precision passes x 4 k16-steps ----
        #pragma unroll
        for (int p = 0; p < 6; p++) {
            const uint32_t aT = smb + aoff[p];
            const uint32_t bT = smb + boff[p];
            #pragma unroll
            for (int ks = 0; ks < 4; ks++) {
                const uint32_t kb = ((uint32_t)(ks * 32) | sel16) ^ laneXor;
                uint32_t afr[2][4], bfr[4][4];
                #pragma unroll
                for (int mt = 0; mt < 2; mt++)
                    ldsm4(afr[mt], aT + ((uint32_t)(mw * 32 + mt * 16) << 7) + rowTerm + kb);
                #pragma unroll
                for (int g = 0; g < 4; g++)
                    ldsm4(bfr[g], bT + ((uint32_t)(nw * 64 + g * 16) << 7) + rowTerm + kb);
                #pragma unroll
                for (int mt = 0; mt < 2; mt++)
                    #pragma unroll
                    for (int g = 0; g < 4; g++) {
                        mma_bf16(acc[mt][2 * g + 0], afr[mt], bfr[g][0], bfr[g][2]);
                        mma_bf16(acc[mt][2 * g + 1], afr[mt], bfr[g][1], bfr[g][3]);
                    }
            }
        }
    }
    __syncthreads();   // stage region dead; reuse as dist[]

    // ---- dist = p_sq - 2*cross (q_sq cancels) ----
    #pragma unroll
    for (int mt = 0; mt < 2; mt++) {
        int cA = mw * 32 + mt * 16 + (lane >> 2);
        float psA = g_psq[b * CC + cA];
        float psB = g_psq[b * CC + cA + 8];
        #pragma unroll
        for (int nt = 0; nt < 8; nt++) {
            int q = nw * 64 + nt * 8 + 2 * (lane & 3);
            float* d0 = &dist[cA * 130 + q];
            float* d1 = &dist[(cA + 8) * 130 + q];
            d0[0] = psA - 2.0f * acc[mt][nt][0];
            d0[1] = psA - 2.0f * acc[mt][nt][1];
            d1[0] = psB - 2.0f * acc[mt][nt][2];
            d1[1] = psB - 2.0f * acc[mt][nt][3];
        }
    }
    __syncthreads();

    // ---- per-query argmin + softmax-CE ----
    const int q = tid & 127, half = tid >> 7, c0 = half * 64;
    float mn = FLT_MAX; int am = 0;
    #pragma unroll 8
    for (int c = 0; c < 64; c++) {
        float v = dist[(c0 + c) * 130 + q];
        if (v < mn) { mn = v; am = c0 + c; }
    }
    redmin[half * 128 + q] = mn;
    redarg[half * 128 + q] = am;
    __syncthreads();

    float mn0 = redmin[q], mn1 = redmin[128 + q];
    float g; int ga;
    if (mn0 <= mn1) { g = mn0; ga = redarg[q]; }
    else            { g = mn1; ga = redarg[128 + q]; }

    float s = 0.0f;
    #pragma unroll 8
    for (int c = 0; c < 64; c++)
        s += expf(g - dist[(c0 + c) * 130 + q]);
    redsum[half * 128 + q] = s;
    __syncthreads();

    float nll = 0.0f; int corr = 0;
    if (tid < 128) {
        float S = redsum[q] + redsum[128 + q];
        int tgt = qtgt[(size_t)b * NQ + q0 + q];
        float tl = dist[tgt * 130 + q];
        nll = tl - g + logf(S);
        corr = (ga == tgt);
        if (pred_out) pred_out[(size_t)b * NQ + q0 + q] = (float)ga;
    }
    __syncthreads();

    float* L = dist;
    int*   C = (int*)(dist + 128);
    if (tid < 128) { L[tid] = nll; C[tid] = corr; }
    __syncthreads();
    for (int s2 = 64; s2 > 0; s2 >>= 1) {
        if (tid < s2) { L[tid] += L[tid + s2]; C[tid] += C[tid + s2]; }
        __syncthreads();
    }
    if (tid == 0) {
        g_loss_part[b * 32 + qt] = L[0];
        g_corr_part[b * 32 + qt] = C[0];
    }
}

// ---------------------------------------------------------------------------
// Kernel 4: deterministic final reduction + tail writes.
// ---------------------------------------------------------------------------
__global__ void finalize_kernel(float* __restrict__ out, int out_size) {
    __shared__ float sl[GEMM_BLOCKS];
    __shared__ int   sc[GEMM_BLOCKS];
    int t = threadIdx.x;
    sl[t] = g_loss_part[t];
    sc[t] = g_corr_part[t];
    __syncthreads();
    for (int s = GEMM_BLOCKS / 2; s > 0; s >>= 1) {
        if (t < s) { sl[t] += sl[t + s]; sc[t] += sc[t + s]; }
        __syncthreads();
    }
    if (t == 0) {
        const float inv = 1.0f / (float)(BB * NQ);
        float loss = sl[0] * inv;
        float accu = (float)sc[0] * inv;
        if (out_size >= BB * NQ + 2) {
            out[BB * NQ] = loss;
            out[BB * NQ + 1] = accu;
        } else if (out_size == 2) {
            out[0] = loss; out[1] = accu;
        } else if (out_size == 1) {
            out[0] = loss;
        }
    }
}

// ---------------------------------------------------------------------------
extern "C" void kernel_launch(void* const* d_in, const int* in_sizes, int n_in,
                              void* d_out, int out_size) {
    const float* sup  = (const float*)d_in[0];
    const float* qry  = (const float*)d_in[1];
    const int*   stgt = (const int*)d_in[2];
    const int*   qtgt = (const int*)d_in[3];
    float* out = (float*)d_out;

    const int proto_smem = (CC * 128 + 128) * sizeof(float);
    cudaFuncSetAttribute(proto_kernel,
                         cudaFuncAttributeMaxDynamicSharedMemorySize, proto_smem);
    cudaFuncSetAttribute(gemm_kernel,
                         cudaFuncAttributeMaxDynamicSharedMemorySize, SMEM_GEMM);

    proto_kernel<<<dim3(4, BB, SPLIT), 128, proto_smem>>>(sup, stgt);
    reduce_kernel<<<dim3(CC, BB), 128>>>();

    float* pred_out = (out_size >= BB * NQ) ? out : nullptr;
    gemm_kernel<<<dim3(NQ / 128, BB), 256, SMEM_GEMM>>>(qry, qtgt, pred_out);

    finalize_kernel<<<1, GEMM_BLOCKS>>>(out, out_size);
}

// round 5
// speedup vs baseline: 3.7722x; 1.9378x over previous
#include <cuda_runtime.h>
#include <cuda_bf16.h>
#include <math.h>
#include <float.h>
#include <stdint.h>

#define BB 16
#define NS 4096
#define NQ 4096
#define DD 512
#define CC 128
#define SPLIT 8
#define GEMM_BLOCKS (BB * (NQ / 128))   // 512
#define MARGIN 1.0f
#define LIST_CAP 4096

// ---------------- static device scratch (no runtime alloc) ----------------
__device__ float g_part[(size_t)SPLIT * BB * 4 * CC * 128];   // 32 MB
__device__ float g_cnt_part[SPLIT * BB * CC];
__device__ __nv_bfloat16 g_proto_h[(size_t)BB * CC * DD];     // [b][c][d] bf16
__device__ float g_proto_f[(size_t)BB * CC * DD];             // [b][c][d] fp32
__device__ float g_psq[BB * CC];
__device__ float g_loss_part[GEMM_BLOCKS];
__device__ int   g_corr_part[GEMM_BLOCKS];

// ---------------- helpers ----------------
__device__ __forceinline__ uint32_t smem_u32(const void* p) {
    uint32_t a;
    asm("{ .reg .u64 t; cvta.to.shared.u64 t, %1; cvt.u32.u64 %0, t; }" : "=r"(a) : "l"(p));
    return a;
}
__device__ __forceinline__ void cp_async16(uint32_t dst, const void* src) {
    asm volatile("cp.async.cg.shared.global [%0], [%1], 16;" :: "r"(dst), "l"(src));
}
__device__ __forceinline__ void cp_commit() {
    asm volatile("cp.async.commit_group;" ::: "memory");
}
__device__ __forceinline__ void cp_wait0() {
    asm volatile("cp.async.wait_group 0;" ::: "memory");
}
__device__ __forceinline__ void ldsm4(uint32_t* r, uint32_t addr) {
    asm volatile("ldmatrix.sync.aligned.m8n8.x4.shared.b16 {%0,%1,%2,%3}, [%4];"
                 : "=r"(r[0]), "=r"(r[1]), "=r"(r[2]), "=r"(r[3]) : "r"(addr));
}
__device__ __forceinline__ void mma_bf16(float* c, const uint32_t* a,
                                         uint32_t b0, uint32_t b1) {
    asm volatile("mma.sync.aligned.m16n8k16.row.col.f32.bf16.bf16.f32 "
                 "{%0,%1,%2,%3}, {%4,%5,%6,%7}, {%8,%9}, {%0,%1,%2,%3};"
                 : "+f"(c[0]), "+f"(c[1]), "+f"(c[2]), "+f"(c[3])
                 : "r"(a[0]), "r"(a[1]), "r"(a[2]), "r"(a[3]), "r"(b0), "r"(b1));
}
__device__ __forceinline__ uint32_t pkbf(float a, float b) {
    __nv_bfloat162 t = __floats2bfloat162_rn(a, b);
    return *reinterpret_cast<uint32_t*>(&t);
}

// ---------------------------------------------------------------------------
// Kernel 1: split prototype accumulation. Grid (4 dg, 16 b, 8 split), 128 thr.
// ---------------------------------------------------------------------------
__global__ void proto_kernel(const float* __restrict__ sup,
                             const int* __restrict__ stgt) {
    extern __shared__ float sm[];
    float* acc = sm;             // [128 c][128 dlane]
    float* cnt = sm + CC * 128;

    const int t = threadIdx.x, dg = blockIdx.x, b = blockIdx.y, sp = blockIdx.z;

    #pragma unroll 4
    for (int c = 0; c < CC; c++) acc[c * 128 + t] = 0.0f;
    cnt[t] = 0.0f;
    __syncthreads();

    const int* tg = stgt + (size_t)b * NS + sp * (NS / SPLIT);
    if (dg == 0)
        for (int n = t; n < NS / SPLIT; n += 128) atomicAdd(&cnt[tg[n]], 1.0f);

    const float* supb = sup + ((size_t)b * NS + sp * (NS / SPLIT)) * DD + dg * 128 + t;
    for (int n0 = 0; n0 < NS / SPLIT; n0 += 16) {
        int cc16[16]; float vv[16];
        #pragma unroll
        for (int u = 0; u < 16; u++) {
            cc16[u] = tg[n0 + u];
            vv[u] = supb[(size_t)(n0 + u) * DD];
        }
        #pragma unroll
        for (int u = 0; u < 16; u++) acc[cc16[u] * 128 + t] += vv[u];
    }
    __syncthreads();

    float* dst = g_part + ((((size_t)sp * BB + b) * 4 + dg) * CC) * 128 + t;
    for (int c = 0; c < CC; c++) dst[(size_t)c * 128] = acc[c * 128 + t];
    if (dg == 0) g_cnt_part[(sp * BB + b) * CC + t] = cnt[t];
}

// ---------------------------------------------------------------------------
// Kernel 2: deterministic reduce -> bf16 + fp32 protos + p_sq.
// Grid (128 c, 16 b), 128 threads.
// ---------------------------------------------------------------------------
__global__ void reduce_kernel() {
    const int c = blockIdx.x, b = blockIdx.y, t = threadIdx.x;

    float cntv = 0.0f;
    #pragma unroll
    for (int s = 0; s < SPLIT; s++) cntv += g_cnt_part[(s * BB + b) * CC + c];
    const float inv = 1.0f / fmaxf(cntv, 1.0f);

    float psq = 0.0f;
    #pragma unroll
    for (int dg = 0; dg < 4; dg++) {
        float v = 0.0f;
        #pragma unroll
        for (int s = 0; s < SPLIT; s++)
            v += g_part[(((size_t)s * BB + b) * 4 + dg) * CC * 128 + (size_t)c * 128 + t];
        float mean = v * inv;
        size_t o = ((size_t)b * CC + c) * DD + dg * 128 + t;
        g_proto_h[o] = __float2bfloat16_rn(mean);
        g_proto_f[o] = mean;
        psq = fmaf(mean, mean, psq);
    }
    __shared__ float r[128];
    r[t] = psq;
    __syncthreads();
    for (int s = 64; s > 0; s >>= 1) {
        if (t < s) r[t] += r[t + s];
        __syncthreads();
    }
    if (t == 0) g_psq[b * CC + c] = r[0];
}

// ---------------------------------------------------------------------------
// Kernel 3: single-pass bf16 mma.sync distance GEMM, double-buffered, with
// fused argmin / candidate-refinement / softmax-CE epilogue.
// Grid (32 qtiles, 16 b), 256 threads.
// Stage buffers: SA0 0, SA1 16384, SB0 32768, SB1 49152 (XOR swizzle).
// Epilogue union: dist[128][130] @0 (66560 B), redmin @66560 (1024),
//   redarg @67584 (1024), redsum @68608 (1024), list @69632 (16384),
//   nlist @86016. Total 86048.
// ---------------------------------------------------------------------------
#define OFF_REDMIN 66560
#define OFF_REDARG 67584
#define OFF_REDSUM 68608
#define OFF_LIST   69632
#define OFF_NLIST  86016
#define SMEM_GEMM  86048

__global__ __launch_bounds__(256, 2)
void gemm_kernel(const float* __restrict__ qry,
                 const int* __restrict__ qtgt,
                 float* __restrict__ pred_out) {
    extern __shared__ char smem[];
    const uint32_t smb = smem_u32(smem);
    float* dist   = (float*)smem;                 // [128 c][130]
    float* redmin = (float*)(smem + OFF_REDMIN);  // [2][128]
    int*   redarg = (int*)  (smem + OFF_REDARG);  // [2][128]
    float* redsum = (float*)(smem + OFF_REDSUM);  // [2][128]
    uint32_t* list = (uint32_t*)(smem + OFF_LIST);
    int* nlist = (int*)(smem + OFF_NLIST);

    const int tid = threadIdx.x, wid = tid >> 5, lane = tid & 31;
    const int mw = wid & 3, nw = wid >> 2;
    const int qt = blockIdx.x, b = blockIdx.y, q0 = qt * 128;

    const float* Qb = qry + ((size_t)b * NQ + q0) * DD;
    const __nv_bfloat16* Ah = g_proto_h + (size_t)b * CC * DD;

    if (tid == 0) *nlist = 0;

    float acc[2][8][4];
    #pragma unroll
    for (int i = 0; i < 2; i++)
        #pragma unroll
        for (int j = 0; j < 8; j++)
            #pragma unroll
            for (int k = 0; k < 4; k++) acc[i][j][k] = 0.0f;

    const int srow = tid >> 3;          // with p*32 offset -> rows 0..127
    const int sc16 = tid & 7;

    const uint32_t rowTerm = (uint32_t)(lane & 15) << 7;
    const uint32_t sel16   = (uint32_t)(lane & 16);
    const uint32_t laneXor = (uint32_t)(lane & 7) << 4;

    // ---- prologue: stage chunk 0 into buffer 0 ----
    {
        #pragma unroll
        for (int p = 0; p < 4; p++) {
            int row = srow + p * 32;
            uint32_t sw = (uint32_t)(row * 128 + sc16 * 16) ^ ((uint32_t)(row & 7) << 4);
            cp_async16(smb + 0 + sw, Ah + (size_t)row * DD + sc16 * 8);
        }
        cp_commit();
        #pragma unroll
        for (int p = 0; p < 4; p++) {
            int row = srow + p * 32;
            const float* src = Qb + (size_t)row * DD + sc16 * 8;
            float4 v0 = *(const float4*)(src);
            float4 v1 = *(const float4*)(src + 4);
            uint32_t sw = (uint32_t)(row * 128 + sc16 * 16) ^ ((uint32_t)(row & 7) << 4);
            *(uint4*)(smem + 32768 + sw) =
                make_uint4(pkbf(v0.x, v0.y), pkbf(v0.z, v0.w), pkbf(v1.x, v1.y), pkbf(v1.z, v1.w));
        }
        cp_wait0();
        __syncthreads();
    }

    for (int ck = 0; ck < 8; ck++) {
        const int cur = ck & 1;
        if (ck < 7) {
            const int k0 = (ck + 1) * 64;
            const uint32_t aBuf = (cur ^ 1) * 16384u;
            const uint32_t bBuf = 32768u + (cur ^ 1) * 16384u;
            #pragma unroll
            for (int p = 0; p < 4; p++) {
                int row = srow + p * 32;
                uint32_t sw = (uint32_t)(row * 128 + sc16 * 16) ^ ((uint32_t)(row & 7) << 4);
                cp_async16(smb + aBuf + sw, Ah + (size_t)row * DD + k0 + sc16 * 8);
            }
            cp_commit();
            #pragma unroll
            for (int p = 0; p < 4; p++) {
                int row = srow + p * 32;
                const float* src = Qb + (size_t)row * DD + k0 + sc16 * 8;
                float4 v0 = *(const float4*)(src);
                float4 v1 = *(const float4*)(src + 4);
                uint32_t sw = (uint32_t)(row * 128 + sc16 * 16) ^ ((uint32_t)(row & 7) << 4);
                *(uint4*)(smem + bBuf + sw) =
                    make_uint4(pkbf(v0.x, v0.y), pkbf(v0.z, v0.w), pkbf(v1.x, v1.y), pkbf(v1.z, v1.w));
            }
        }

        // ---- compute current buffer ----
        {
            const uint32_t aT = smb + cur * 16384u;
            const uint32_t bT = smb + 32768u + cur * 16384u;
            #pragma unroll
            for (int ks = 0; ks < 4; ks++) {
                const uint32_t kb = ((uint32_t)(ks * 32) | sel16) ^ laneXor;
                uint32_t afr[2][4], bfr[4][4];
                #pragma unroll
                for (int mt = 0; mt < 2; mt++)
                    ldsm4(afr[mt], aT + ((uint32_t)(mw * 32 + mt * 16) << 7) + rowTerm + kb);
                #pragma unroll
                for (int g = 0; g < 4; g++)
                    ldsm4(bfr[g], bT + ((uint32_t)(nw * 64 + g * 16) << 7) + rowTerm + kb);
                #pragma unroll
                for (int mt = 0; mt < 2; mt++)
                    #pragma unroll
                    for (int g = 0; g < 4; g++) {
                        mma_bf16(acc[mt][2 * g + 0], afr[mt], bfr[g][0], bfr[g][2]);
                        mma_bf16(acc[mt][2 * g + 1], afr[mt], bfr[g][1], bfr[g][3]);
                    }
            }
        }
        if (ck < 7) cp_wait0();
        __syncthreads();
    }

    // ---- dist = p_sq - 2*cross (q_sq cancels in argmin/softmax/NLL) ----
    #pragma unroll
    for (int mt = 0; mt < 2; mt++) {
        int cA = mw * 32 + mt * 16 + (lane >> 2);
        float psA = g_psq[b * CC + cA];
        float psB = g_psq[b * CC + cA + 8];
        #pragma unroll
        for (int nt = 0; nt < 8; nt++) {
            int q = nw * 64 + nt * 8 + 2 * (lane & 3);
            float* d0 = &dist[cA * 130 + q];
            float* d1 = &dist[(cA + 8) * 130 + q];
            d0[0] = psA - 2.0f * acc[mt][nt][0];
            d0[1] = psA - 2.0f * acc[mt][nt][1];
            d1[0] = psB - 2.0f * acc[mt][nt][2];
            d1[1] = psB - 2.0f * acc[mt][nt][3];
        }
    }
    __syncthreads();

    // ---- pass 1: approximate per-query min + candidate collection ----
    if (tid < 128) {
        const int q = tid;
        float mn = FLT_MAX;
        #pragma unroll 8
        for (int c = 0; c < CC; c++) {
            float v = dist[c * 130 + q];
            if (v < mn) mn = v;
        }
        int cnt = 0;
        #pragma unroll 8
        for (int c = 0; c < CC; c++)
            cnt += (dist[c * 130 + q] < mn + MARGIN);
        if (cnt > 1) {
            for (int c = 0; c < CC; c++) {
                if (dist[c * 130 + q] < mn + MARGIN) {
                    int slot = atomicAdd(nlist, 1);
                    if (slot < LIST_CAP)
                        list[slot] = ((uint32_t)c << 16) | (uint32_t)q;
                }
            }
        }
    }
    __syncthreads();

    // ---- refinement: exact fp32 dist for ambiguous (q, c) pairs ----
    {
        int n = *nlist;
        if (n > LIST_CAP) n = LIST_CAP;
        for (int i = wid; i < n; i += 8) {
            uint32_t e = list[i];
            int c = (int)(e >> 16), q = (int)(e & 0xFFFFu);
            const float4* P  = (const float4*)(g_proto_f + ((size_t)b * CC + c) * DD);
            const float4* Q4 = (const float4*)(Qb + (size_t)q * DD);
            float s = 0.0f;
            #pragma unroll
            for (int j = 0; j < 4; j++) {
                float4 a = P[lane + j * 32];
                float4 w = Q4[lane + j * 32];
                s = fmaf(a.x, w.x, s);
                s = fmaf(a.y, w.y, s);
                s = fmaf(a.z, w.z, s);
                s = fmaf(a.w, w.w, s);
            }
            #pragma unroll
            for (int o = 16; o > 0; o >>= 1)
                s += __shfl_xor_sync(0xFFFFFFFFu, s, o);
            if (lane == 0)
                dist[c * 130 + q] = g_psq[b * CC + c] - 2.0f * s;
        }
    }
    __syncthreads();

    // ---- final epilogue on refined dist: argmin + softmax-CE ----
    const int q = tid & 127, half = tid >> 7, c0 = half * 64;
    float mn = FLT_MAX; int am = 0;
    #pragma unroll 8
    for (int c = 0; c < 64; c++) {
        float v = dist[(c0 + c) * 130 + q];
        if (v < mn) { mn = v; am = c0 + c; }
    }
    redmin[half * 128 + q] = mn;
    redarg[half * 128 + q] = am;
    __syncthreads();

    float mn0 = redmin[q], mn1 = redmin[128 + q];
    float g; int ga;
    if (mn0 <= mn1) { g = mn0; ga = redarg[q]; }
    else            { g = mn1; ga = redarg[128 + q]; }

    float s = 0.0f;
    #pragma unroll 8
    for (int c = 0; c < 64; c++)
        s += expf(g - dist[(c0 + c) * 130 + q]);
    redsum[half * 128 + q] = s;
    __syncthreads();

    float nll = 0.0f; int corr = 0;
    if (tid < 128) {
        float S = redsum[q] + redsum[128 + q];
        int tgt = qtgt[(size_t)b * NQ + q0 + q];
        float tl = dist[tgt * 130 + q];
        nll = tl - g + logf(S);
        corr = (ga == tgt);
        if (pred_out) pred_out[(size_t)b * NQ + q0 + q] = (float)ga;
    }
    __syncthreads();

    float* L = redmin;                 // reuse (values dead)
    int*   C = redarg;
    if (tid < 128) { L[tid] = nll; C[tid] = corr; }
    __syncthreads();
    for (int s2 = 64; s2 > 0; s2 >>= 1) {
        if (tid < s2) { L[tid] += L[tid + s2]; C[tid] += C[tid + s2]; }
        __syncthreads();
    }
    if (tid == 0) {
        g_loss_part[b * 32 + qt] = L[0];
        g_corr_part[b * 32 + qt] = C[0];
    }
}

// ---------------------------------------------------------------------------
// Kernel 4: deterministic final reduction + tail writes.
// ---------------------------------------------------------------------------
__global__ void finalize_kernel(float* __restrict__ out, int out_size) {
    __shared__ float sl[GEMM_BLOCKS];
    __shared__ int   sc[GEMM_BLOCKS];
    int t = threadIdx.x;
    sl[t] = g_loss_part[t];
    sc[t] = g_corr_part[t];
    __syncthreads();
    for (int s = GEMM_BLOCKS / 2; s > 0; s >>= 1) {
        if (t < s) { sl[t] += sl[t + s]; sc[t] += sc[t + s]; }
        __syncthreads();
    }
    if (t == 0) {
        const float inv = 1.0f / (float)(BB * NQ);
        float loss = sl[0] * inv;
        float accu = (float)sc[0] * inv;
        if (out_size >= BB * NQ + 2) {
            out[BB * NQ] = loss;
            out[BB * NQ + 1] = accu;
        } else if (out_size == 2) {
            out[0] = loss; out[1] = accu;
        } else if (out_size == 1) {
            out[0] = loss;
        }
    }
}

// ---------------------------------------------------------------------------
extern "C" void kernel_launch(void* const* d_in, const int* in_sizes, int n_in,
                              void* d_out, int out_size) {
    const float* sup  = (const float*)d_in[0];
    const float* qry  = (const float*)d_in[1];
    const int*   stgt = (const int*)d_in[2];
    const int*   qtgt = (const int*)d_in[3];
    float* out = (float*)d_out;

    const int proto_smem = (CC * 128 + 128) * sizeof(float);
    cudaFuncSetAttribute(proto_kernel,
                         cudaFuncAttributeMaxDynamicSharedMemorySize, proto_smem);
    cudaFuncSetAttribute(gemm_kernel,
                         cudaFuncAttributeMaxDynamicSharedMemorySize, SMEM_GEMM);

    proto_kernel<<<dim3(4, BB, SPLIT), 128, proto_smem>>>(sup, stgt);
    reduce_kernel<<<dim3(CC, BB), 128>>>();

    float* pred_out = (out_size >= BB * NQ) ? out : nullptr;
    gemm_kernel<<<dim3(NQ / 128, BB), 256, SMEM_GEMM>>>(qry, qtgt, pred_out);

    finalize_kernel<<<1, GEMM_BLOCKS>>>(out, out_size);
}

// round 6
// speedup vs baseline: 4.1319x; 1.0954x over previous
#include <cuda_runtime.h>
#include <cuda_fp16.h>
#include <cuda_bf16.h>
#include <math.h>
#include <float.h>
#include <stdint.h>

#define BB 16
#define NS 4096
#define NQ 4096
#define DD 512
#define CC 128
#define SPLIT 8
#define QTILE 64
#define GEMM_BLOCKS (BB * (NQ / QTILE))   // 1024
#define MARGIN 0.25f
#define LIST_CAP 1024

// ---------------- static device scratch (no runtime alloc) ----------------
__device__ float g_part[(size_t)SPLIT * BB * 4 * CC * 128];   // 32 MB
__device__ float g_cnt_part[SPLIT * BB * CC];
__device__ __half g_proto_h[(size_t)BB * CC * DD];            // [b][c][d] fp16
__device__ float  g_proto_f[(size_t)BB * CC * DD];            // [b][c][d] fp32
__device__ float  g_psq[BB * CC];
__device__ float  g_loss_part[GEMM_BLOCKS];
__device__ int    g_corr_part[GEMM_BLOCKS];

// ---------------- helpers ----------------
__device__ __forceinline__ uint32_t smem_u32(const void* p) {
    uint32_t a;
    asm("{ .reg .u64 t; cvta.to.shared.u64 t, %1; cvt.u32.u64 %0, t; }" : "=r"(a) : "l"(p));
    return a;
}
__device__ __forceinline__ void cp_async16(uint32_t dst, const void* src) {
    asm volatile("cp.async.cg.shared.global [%0], [%1], 16;" :: "r"(dst), "l"(src));
}
__device__ __forceinline__ void cp_commit() {
    asm volatile("cp.async.commit_group;" ::: "memory");
}
__device__ __forceinline__ void cp_wait0() {
    asm volatile("cp.async.wait_group 0;" ::: "memory");
}
__device__ __forceinline__ void ldsm4(uint32_t* r, uint32_t addr) {
    asm volatile("ldmatrix.sync.aligned.m8n8.x4.shared.b16 {%0,%1,%2,%3}, [%4];"
                 : "=r"(r[0]), "=r"(r[1]), "=r"(r[2]), "=r"(r[3]) : "r"(addr));
}
__device__ __forceinline__ void mma_f16(float* c, const uint32_t* a,
                                        uint32_t b0, uint32_t b1) {
    asm volatile("mma.sync.aligned.m16n8k16.row.col.f32.f16.f16.f32 "
                 "{%0,%1,%2,%3}, {%4,%5,%6,%7}, {%8,%9}, {%0,%1,%2,%3};"
                 : "+f"(c[0]), "+f"(c[1]), "+f"(c[2]), "+f"(c[3])
                 : "r"(a[0]), "r"(a[1]), "r"(a[2]), "r"(a[3]), "r"(b0), "r"(b1));
}
__device__ __forceinline__ uint32_t pkhf(float a, float b) {
    __half2 t = __floats2half2_rn(a, b);
    return *reinterpret_cast<uint32_t*>(&t);
}

// ---------------------------------------------------------------------------
// Kernel 1: split prototype accumulation. Grid (4 dg, 16 b, 8 split), 128 thr.
// ---------------------------------------------------------------------------
__global__ void proto_kernel(const float* __restrict__ sup,
                             const int* __restrict__ stgt) {
    extern __shared__ float sm[];
    float* acc = sm;             // [128 c][128 dlane]
    float* cnt = sm + CC * 128;

    const int t = threadIdx.x, dg = blockIdx.x, b = blockIdx.y, sp = blockIdx.z;

    #pragma unroll 4
    for (int c = 0; c < CC; c++) acc[c * 128 + t] = 0.0f;
    cnt[t] = 0.0f;
    __syncthreads();

    const int* tg = stgt + (size_t)b * NS + sp * (NS / SPLIT);
    if (dg == 0)
        for (int n = t; n < NS / SPLIT; n += 128) atomicAdd(&cnt[tg[n]], 1.0f);

    const float* supb = sup + ((size_t)b * NS + sp * (NS / SPLIT)) * DD + dg * 128 + t;
    for (int n0 = 0; n0 < NS / SPLIT; n0 += 16) {
        int cc16[16]; float vv[16];
        #pragma unroll
        for (int u = 0; u < 16; u++) {
            cc16[u] = tg[n0 + u];
            vv[u] = supb[(size_t)(n0 + u) * DD];
        }
        #pragma unroll
        for (int u = 0; u < 16; u++) acc[cc16[u] * 128 + t] += vv[u];
    }
    __syncthreads();

    float* dst = g_part + ((((size_t)sp * BB + b) * 4 + dg) * CC) * 128 + t;
    for (int c = 0; c < CC; c++) dst[(size_t)c * 128] = acc[c * 128 + t];
    if (dg == 0) g_cnt_part[(sp * BB + b) * CC + t] = cnt[t];
}

// ---------------------------------------------------------------------------
// Kernel 2: deterministic reduce -> fp16 + fp32 protos + p_sq.
// Grid (128 c, 16 b), 128 threads.
// ---------------------------------------------------------------------------
__global__ void reduce_kernel() {
    const int c = blockIdx.x, b = blockIdx.y, t = threadIdx.x;

    float cntv = 0.0f;
    #pragma unroll
    for (int s = 0; s < SPLIT; s++) cntv += g_cnt_part[(s * BB + b) * CC + c];
    const float inv = 1.0f / fmaxf(cntv, 1.0f);

    float psq = 0.0f;
    #pragma unroll
    for (int dg = 0; dg < 4; dg++) {
        float v = 0.0f;
        #pragma unroll
        for (int s = 0; s < SPLIT; s++)
            v += g_part[(((size_t)s * BB + b) * 4 + dg) * CC * 128 + (size_t)c * 128 + t];
        float mean = v * inv;
        size_t o = ((size_t)b * CC + c) * DD + dg * 128 + t;
        g_proto_h[o] = __float2half_rn(mean);
        g_proto_f[o] = mean;
        psq = fmaf(mean, mean, psq);
    }
    __shared__ float r[128];
    r[t] = psq;
    __syncthreads();
    for (int s = 64; s > 0; s >>= 1) {
        if (t < s) r[t] += r[t + s];
        __syncthreads();
    }
    if (t == 0) g_psq[b * CC + c] = r[0];
}

// ---------------------------------------------------------------------------
// Kernel 3: single-pass fp16 mma.sync distance GEMM (128c x 64q tiles),
// pipelined staging, fused argmin / refinement / softmax-CE epilogue.
// Grid (64 qtiles, 16 b), 256 threads, 3 CTA/SM.
// Stage: SA0@0(16K) SA1@16K SB0@32K(8K) SB1@40K -> 48K total.
// Epilogue union @0: dist[128][66] (33792), redmin@33792(1K), redarg@34816(1K),
//   redsum@35840(1K), gmin@36864, garg@37120, percnt@37376, list@37632(4K),
//   nlist@41728.
// ---------------------------------------------------------------------------
#define OFF_RMIN  33792
#define OFF_RARG  34816
#define OFF_RSUM  35840
#define OFF_GMIN  36864
#define OFF_GARG  37120
#define OFF_PCNT  37376
#define OFF_LIST  37632
#define OFF_NLIST 41728
#define SMEM_GEMM 49152

__global__ __launch_bounds__(256, 3)
void gemm_kernel(const float* __restrict__ qry,
                 const int* __restrict__ qtgt,
                 float* __restrict__ pred_out) {
    extern __shared__ char smem[];
    const uint32_t smb = smem_u32(smem);
    float* dist   = (float*)smem;                 // [128 c][66]
    float* redmin = (float*)(smem + OFF_RMIN);    // [4][64]
    int*   redarg = (int*)  (smem + OFF_RARG);
    float* redsum = (float*)(smem + OFF_RSUM);
    float* gmin   = (float*)(smem + OFF_GMIN);    // [64]
    int*   garg   = (int*)  (smem + OFF_GARG);
    int*   percnt = (int*)  (smem + OFF_PCNT);
    uint32_t* list = (uint32_t*)(smem + OFF_LIST);
    int* nlist = (int*)(smem + OFF_NLIST);

    const int tid = threadIdx.x, wid = tid >> 5, lane = tid & 31;
    const int mw = wid & 3, nw = wid >> 2;        // mw: 32 classes, nw: 32 queries
    const int qt = blockIdx.x, b = blockIdx.y, q0 = qt * QTILE;

    const float* Qb = qry + ((size_t)b * NQ + q0) * DD;
    const __half* Ah = g_proto_h + (size_t)b * CC * DD;

    float acc[2][4][4];
    #pragma unroll
    for (int i = 0; i < 2; i++)
        #pragma unroll
        for (int j = 0; j < 4; j++)
            #pragma unroll
            for (int k = 0; k < 4; k++) acc[i][j][k] = 0.0f;

    const uint32_t rowTerm = (uint32_t)(lane & 15) << 7;
    const uint32_t sel16   = (uint32_t)(lane & 16);
    const uint32_t laneXor = (uint32_t)(lane & 7) << 4;

    // ---- prologue: stage chunk 0 into buffer 0 ----
    {
        #pragma unroll
        for (int p = 0; p < 4; p++) {
            int idx = p * 256 + tid;              // A: 1024 slots of 16B
            int row = idx >> 3, c16 = idx & 7;
            uint32_t sw = (uint32_t)(row * 128 + c16 * 16) ^ ((uint32_t)(row & 7) << 4);
            cp_async16(smb + 0 + sw, Ah + (size_t)row * DD + c16 * 8);
        }
        cp_commit();
        #pragma unroll
        for (int p = 0; p < 2; p++) {
            int idx = p * 256 + tid;              // B: 512 slots of 16B
            int row = idx >> 3, c16 = idx & 7;
            const float* src = Qb + (size_t)row * DD + c16 * 8;
            float4 v0 = *(const float4*)(src);
            float4 v1 = *(const float4*)(src + 4);
            uint32_t sw = (uint32_t)(row * 128 + c16 * 16) ^ ((uint32_t)(row & 7) << 4);
            *(uint4*)(smem + 32768 + sw) =
                make_uint4(pkhf(v0.x, v0.y), pkhf(v0.z, v0.w), pkhf(v1.x, v1.y), pkhf(v1.z, v1.w));
        }
        cp_wait0();
        __syncthreads();
    }

    for (int ck = 0; ck < 8; ck++) {
        const int cur = ck & 1;
        float4 bv0[2], bv1[2];
        if (ck < 7) {
            const int k0 = (ck + 1) * 64;
            const uint32_t aBuf = (cur ^ 1) * 16384u;
            #pragma unroll
            for (int p = 0; p < 4; p++) {
                int idx = p * 256 + tid;
                int row = idx >> 3, c16 = idx & 7;
                uint32_t sw = (uint32_t)(row * 128 + c16 * 16) ^ ((uint32_t)(row & 7) << 4);
                cp_async16(smb + aBuf + sw, Ah + (size_t)row * DD + k0 + c16 * 8);
            }
            cp_commit();
            // issue B loads for next chunk (consumed after mma)
            #pragma unroll
            for (int p = 0; p < 2; p++) {
                int idx = p * 256 + tid;
                int row = idx >> 3, c16 = idx & 7;
                const float* src = Qb + (size_t)row * DD + k0 + c16 * 8;
                bv0[p] = *(const float4*)(src);
                bv1[p] = *(const float4*)(src + 4);
            }
        }

        // ---- compute current buffer ----
        {
            const uint32_t aT = smb + cur * 16384u;
            const uint32_t bT = smb + 32768u + cur * 8192u;
            #pragma unroll
            for (int ks = 0; ks < 4; ks++) {
                const uint32_t kb = ((uint32_t)(ks * 32) | sel16) ^ laneXor;
                uint32_t afr[2][4], bfr[2][4];
                #pragma unroll
                for (int mt = 0; mt < 2; mt++)
                    ldsm4(afr[mt], aT + ((uint32_t)(mw * 32 + mt * 16) << 7) + rowTerm + kb);
                #pragma unroll
                for (int g = 0; g < 2; g++)
                    ldsm4(bfr[g], bT + ((uint32_t)(nw * 32 + g * 16) << 7) + rowTerm + kb);
                #pragma unroll
                for (int mt = 0; mt < 2; mt++)
                    #pragma unroll
                    for (int g = 0; g < 2; g++) {
                        mma_f16(acc[mt][2 * g + 0], afr[mt], bfr[g][0], bfr[g][2]);
                        mma_f16(acc[mt][2 * g + 1], afr[mt], bfr[g][1], bfr[g][3]);
                    }
            }
        }

        if (ck < 7) {
            const uint32_t bBuf = 32768u + (cur ^ 1) * 8192u;
            #pragma unroll
            for (int p = 0; p < 2; p++) {
                int idx = p * 256 + tid;
                int row = idx >> 3, c16 = idx & 7;
                uint32_t sw = (uint32_t)(row * 128 + c16 * 16) ^ ((uint32_t)(row & 7) << 4);
                *(uint4*)(smem + bBuf + sw) =
                    make_uint4(pkhf(bv0[p].x, bv0[p].y), pkhf(bv0[p].z, bv0[p].w),
                               pkhf(bv1[p].x, bv1[p].y), pkhf(bv1[p].z, bv1[p].w));
            }
            cp_wait0();
        }
        __syncthreads();
    }

    // ---- dist = p_sq - 2*cross (q_sq cancels) ----
    #pragma unroll
    for (int mt = 0; mt < 2; mt++) {
        int cA = mw * 32 + mt * 16 + (lane >> 2);
        float psA = g_psq[b * CC + cA];
        float psB = g_psq[b * CC + cA + 8];
        #pragma unroll
        for (int nt = 0; nt < 4; nt++) {
            int q = nw * 32 + nt * 8 + 2 * (lane & 3);
            float* d0 = &dist[cA * 66 + q];
            float* d1 = &dist[(cA + 8) * 66 + q];
            d0[0] = psA - 2.0f * acc[mt][nt][0];
            d0[1] = psA - 2.0f * acc[mt][nt][1];
            d1[0] = psB - 2.0f * acc[mt][nt][2];
            d1[1] = psB - 2.0f * acc[mt][nt][3];
        }
    }
    if (tid == 0) *nlist = 0;
    if (tid < QTILE) percnt[tid] = 0;
    __syncthreads();

    // ---- pass 1: per-quarter min -> global approx min ----
    const int q = tid & 63, qr = tid >> 6, c0 = qr * 32;
    {
        float mn = FLT_MAX; int am = 0;
        #pragma unroll 8
        for (int c = 0; c < 32; c++) {
            float v = dist[(c0 + c) * 66 + q];
            if (v < mn) { mn = v; am = c0 + c; }
        }
        redmin[qr * 64 + q] = mn;
        redarg[qr * 64 + q] = am;
    }
    __syncthreads();
    if (tid < QTILE) {
        float g = FLT_MAX; int ga = 0;
        #pragma unroll
        for (int i = 0; i < 4; i++) {
            float v = redmin[i * 64 + tid];
            if (v < g) { g = v; ga = redarg[i * 64 + tid]; }
        }
        gmin[tid] = g; garg[tid] = ga;
    }
    __syncthreads();

    // ---- candidate counting + collection ----
    {
        float g = gmin[q];
        int cnt = 0;
        #pragma unroll 8
        for (int c = 0; c < 32; c++)
            cnt += (dist[(c0 + c) * 66 + q] < g + MARGIN);
        if (cnt) atomicAdd(&percnt[q], cnt);
    }
    __syncthreads();
    {
        float g = gmin[q];
        if (percnt[q] > 1) {
            for (int c = 0; c < 32; c++) {
                if (dist[(c0 + c) * 66 + q] < g + MARGIN) {
                    int slot = atomicAdd(nlist, 1);
                    if (slot < LIST_CAP)
                        list[slot] = ((uint32_t)(c0 + c) << 16) | (uint32_t)q;
                }
            }
        }
    }
    __syncthreads();

    // ---- refinement: exact fp32 dist for ambiguous (q, c) pairs ----
    {
        int n = *nlist;
        if (n > LIST_CAP) n = LIST_CAP;
        for (int i = wid; i < n; i += 8) {
            uint32_t e = list[i];
            int c = (int)(e >> 16), qq = (int)(e & 0xFFFFu);
            const float4* P  = (const float4*)(g_proto_f + ((size_t)b * CC + c) * DD);
            const float4* Q4 = (const float4*)(Qb + (size_t)qq * DD);
            float s = 0.0f;
            #pragma unroll
            for (int j = 0; j < 4; j++) {
                float4 a = P[lane + j * 32];
                float4 w = Q4[lane + j * 32];
                s = fmaf(a.x, w.x, s);
                s = fmaf(a.y, w.y, s);
                s = fmaf(a.z, w.z, s);
                s = fmaf(a.w, w.w, s);
            }
            #pragma unroll
            for (int o = 16; o > 0; o >>= 1)
                s += __shfl_xor_sync(0xFFFFFFFFu, s, o);
            if (lane == 0)
                dist[c * 66 + qq] = g_psq[b * CC + c] - 2.0f * s;
        }
    }
    __syncthreads();

    // ---- final argmin on refined dist ----
    {
        float mn = FLT_MAX; int am = 0;
        #pragma unroll 8
        for (int c = 0; c < 32; c++) {
            float v = dist[(c0 + c) * 66 + q];
            if (v < mn) { mn = v; am = c0 + c; }
        }
        redmin[qr * 64 + q] = mn;
        redarg[qr * 64 + q] = am;
    }
    __syncthreads();
    if (tid < QTILE) {
        float g = FLT_MAX; int ga = 0;
        #pragma unroll
        for (int i = 0; i < 4; i++) {
            float v = redmin[i * 64 + tid];
            if (v < g) { g = v; ga = redarg[i * 64 + tid]; }
        }
        gmin[tid] = g; garg[tid] = ga;
    }
    __syncthreads();

    // ---- softmax-CE ----
    {
        float g = gmin[q];
        float s = 0.0f;
        #pragma unroll 8
        for (int c = 0; c < 32; c++)
            s += expf(g - dist[(c0 + c) * 66 + q]);
        redsum[qr * 64 + q] = s;
    }
    __syncthreads();

    if (tid < QTILE) {
        float S = redsum[tid] + redsum[64 + tid] + redsum[128 + tid] + redsum[192 + tid];
        int tgt = qtgt[(size_t)b * NQ + q0 + tid];
        float tl = dist[tgt * 66 + tid];
        float nll = tl - gmin[tid] + logf(S);
        int corr = (garg[tid] == tgt);
        if (pred_out) pred_out[(size_t)b * NQ + q0 + tid] = (float)garg[tid];
        redmin[tid] = nll;           // reuse for block reduce
        redarg[tid] = corr;
    }
    __syncthreads();
    for (int s2 = 32; s2 > 0; s2 >>= 1) {
        if (tid < s2) { redmin[tid] += redmin[tid + s2]; redarg[tid] += redarg[tid + s2]; }
        __syncthreads();
    }
    if (tid == 0) {
        g_loss_part[b * (NQ / QTILE) + qt] = redmin[0];
        g_corr_part[b * (NQ / QTILE) + qt] = redarg[0];
    }
}

// ---------------------------------------------------------------------------
// Kernel 4: deterministic final reduction + tail writes. 1024 threads.
// ---------------------------------------------------------------------------
__global__ void finalize_kernel(float* __restrict__ out, int out_size) {
    __shared__ float sl[GEMM_BLOCKS];
    __shared__ int   sc[GEMM_BLOCKS];
    int t = threadIdx.x;
    sl[t] = g_loss_part[t];
    sc[t] = g_corr_part[t];
    __syncthreads();
    for (int s = GEMM_BLOCKS / 2; s > 0; s >>= 1) {
        if (t < s) { sl[t] += sl[t + s]; sc[t] += sc[t + s]; }
        __syncthreads();
    }
    if (t == 0) {
        const float inv = 1.0f / (float)(BB * NQ);
        float loss = sl[0] * inv;
        float accu = (float)sc[0] * inv;
        if (out_size >= BB * NQ + 2) {
            out[BB * NQ] = loss;
            out[BB * NQ + 1] = accu;
        } else if (out_size == 2) {
            out[0] = loss; out[1] = accu;
        } else if (out_size == 1) {
            out[0] = loss;
        }
    }
}

// ---------------------------------------------------------------------------
extern "C" void kernel_launch(void* const* d_in, const int* in_sizes, int n_in,
                              void* d_out, int out_size) {
    const float* sup  = (const float*)d_in[0];
    const float* qry  = (const float*)d_in[1];
    const int*   stgt = (const int*)d_in[2];
    const int*   qtgt = (const int*)d_in[3];
    float* out = (float*)d_out;

    const int proto_smem = (CC * 128 + 128) * sizeof(float);
    cudaFuncSetAttribute(proto_kernel,
                         cudaFuncAttributeMaxDynamicSharedMemorySize, proto_smem);
    cudaFuncSetAttribute(gemm_kernel,
                         cudaFuncAttributeMaxDynamicSharedMemorySize, SMEM_GEMM);

    proto_kernel<<<dim3(4, BB, SPLIT), 128, proto_smem>>>(sup, stgt);
    reduce_kernel<<<dim3(CC, BB), 128>>>();

    float* pred_out = (out_size >= BB * NQ) ? out : nullptr;
    gemm_kernel<<<dim3(NQ / QTILE, BB), 256, SMEM_GEMM>>>(qry, qtgt, pred_out);

    finalize_kernel<<<1, GEMM_BLOCKS>>>(out, out_size);
}